// round 17
// baseline (speedup 1.0000x reference)
#include <cuda_runtime.h>
#include <cuda_bf16.h>

#define OUT_W    256
#define IMG_W    512
#define NBLK     512            // (ii in 256) x (i-half h in 2)
#define SK_T     16             // K rows per block
#define SK_W     388            // bf16x2 words per K row; 1552B = 16 mod 128
#define SREV_W   522            // padded reversed-row length in u32 words
#define OFF_K     0
#define OFF_SREV  24832         // 16*388*4
#define OFF_SREVB 26920         // + 522*4
#define SMEM_BYTES 29008

__device__ float g_part[2 * 256 * 4096];        // 8 MB [h][ii][j][i16]
__device__ float g_red[32 * 4096];              // 512 KB [h*16+seg][j][i16]

__device__ __forceinline__ float frcp(float x) {
    float r; asm("rcp.approx.f32 %0, %1;" : "=f"(r) : "f"(x)); return r;
}
__device__ __forceinline__ void mma_bf16(float* d, unsigned a0, unsigned a1,
                                         unsigned a2, unsigned a3,
                                         unsigned b0, unsigned b1) {
    asm volatile(
        "mma.sync.aligned.m16n8k16.row.col.f32.bf16.bf16.f32 "
        "{%0,%1,%2,%3}, {%4,%5,%6,%7}, {%8,%9}, {%0,%1,%2,%3};"
        : "+f"(d[0]), "+f"(d[1]), "+f"(d[2]), "+f"(d[3])
        : "r"(a0), "r"(a1), "r"(a2), "r"(a3), "r"(b0), "r"(b1));
}

// ---------------------------------------------------------------------------
// Block (ii, h): one image row ii, i in [16h,16h+16). 8 warps = (wj: j-strip
// [64wj,64wj+64), 4 m x 2 n tiles) x (se: e-half, 18 k-steps). Mainloop =
// R10/R14-proven naive body. NEW epilogue: fragments staged into a
// [256 j][16 i] SMEM tile (dead K region), se-halves merged there, then ONE
// contiguous 16 KB float4 copy-out per block — kills the scattered-4B-STG
// sector tax (~8x write amplification) present in all prior rounds.
// ---------------------------------------------------------------------------
__global__ void __launch_bounds__(256, 4)
conv_mma_kernel(const float* __restrict__ img, const float* __restrict__ pos) {
    extern __shared__ char smem[];
    unsigned*      skw = (unsigned*)(smem + OFF_K);
    __nv_bfloat16* sr  = (__nv_bfloat16*)(smem + OFF_SREV);   // reversed row
    __nv_bfloat16* srB = (__nv_bfloat16*)(smem + OFF_SREVB);  // shifted +1

    const int ii  = blockIdx.x >> 1;
    const int h   = blockIdx.x & 1;
    const int tid = threadIdx.x;
    const float p0 = pos[0], p1 = pos[1];

    // ---- stage reversed image row (bf16): sr[z] = img[ii][767-z], z in [256,767]
    for (int z = tid; z < 2 * SREV_W; z += 256) {
        float v0 = (z >= 256 && z <= 767) ? img[ii * IMG_W + (767 - z)] : 0.f;
        int z1 = z + 1;
        float v1 = (z1 >= 256 && z1 <= 767) ? img[ii * IMG_W + (767 - z1)] : 0.f;
        sr [z] = __float2bfloat16_rn(v0);
        srB[z] = __float2bfloat16_rn(v1);
    }
    // ---- K rows: row t serves i = 16h + t  (d-255 = 16h + t - ii)
    for (int t = 0; t < SK_T; t++) {
        float dx  = (float)(16 * h + t - ii) + p0;
        float dx2 = dx * dx;
        for (int u = tid; u < SK_W; u += 256) {
            float dy0 = (float)(2 * u - 511) + p1;
            float dy1 = dy0 + 1.0f;
            float v0 = (2 * u     < 767) ? frcp(fmaf(dy0, dy0, dx2)) : 0.f;
            float v1 = (2 * u + 1 < 767) ? frcp(fmaf(dy1, dy1, dx2)) : 0.f;
            unsigned wv;
            asm("cvt.rn.bf16x2.f32 %0, %1, %2;" : "=r"(wv) : "f"(v1), "f"(v0));
            skw[t * SK_W + u] = wv;
        }
    }
    __syncthreads();

    const int w    = tid >> 5;
    const int wj   = w & 3;           // j strip [64wj, 64wj+64)
    const int se   = w >> 2;          // e-half: k-steps q in [18se, 18se+18)
    const int lane = tid & 31;
    const int r    = lane >> 2;
    const int c    = lane & 3;
    const int sel  = r & 1;

    const unsigned* pA = (const unsigned*)(sel ? srB : sr)
                         + ((2 * c - 64 * wj - r + 256 - sel) >> 1);
    const unsigned* pB = skw + r * SK_W + c;

    float acc[4][2][4];
#pragma unroll
    for (int m = 0; m < 4; m++)
#pragma unroll
        for (int n = 0; n < 2; n++)
#pragma unroll
            for (int k = 0; k < 4; k++) acc[m][n][k] = 0.f;

    // k-steps q in [18se, 18se+18): e-words [32wj+8q, +8)  (R10-proven body)
#pragma unroll 1
    for (int q = 18 * se; q < 18 * se + 18; q++) {
        const int ew = 32 * wj + 8 * q;
        unsigned W[9];
#pragma unroll
        for (int k = 0; k < 9; k++) W[k] = pA[ew + 4 - 4 * k];
        unsigned b00 = pB[ew],            b01 = pB[ew + 4];
        unsigned b10 = pB[8 * SK_W + ew], b11 = pB[8 * SK_W + ew + 4];
#pragma unroll
        for (int m = 0; m < 4; m++) {
            mma_bf16(acc[m][0], W[2*m+1], W[2*m+2], W[2*m], W[2*m+1], b00, b01);
            mma_bf16(acc[m][1], W[2*m+1], W[2*m+2], W[2*m], W[2*m+1], b10, b11);
        }
    }

    // ---- epilogue: stage + merge in SMEM tile [256 j][16 i], then coalesced out
    float* tile = (float*)smem;                 // 16 KB in dead K region
    __syncthreads();
    if (se == 1) {
#pragma unroll
        for (int m = 0; m < 4; m++) {
            const int j0 = 64 * wj + 16 * m + r;
#pragma unroll
            for (int nn = 0; nn < 2; nn++) {
                const int il = 8 * nn + 2 * c;
                tile[(j0    ) * 16 + il    ] = acc[m][nn][0];
                tile[(j0    ) * 16 + il + 1] = acc[m][nn][1];
                tile[(j0 + 8) * 16 + il    ] = acc[m][nn][2];
                tile[(j0 + 8) * 16 + il + 1] = acc[m][nn][3];
            }
        }
    }
    __syncthreads();
    if (se == 0) {
#pragma unroll
        for (int m = 0; m < 4; m++) {
            const int j0 = 64 * wj + 16 * m + r;
#pragma unroll
            for (int nn = 0; nn < 2; nn++) {
                const int il = 8 * nn + 2 * c;
                tile[(j0    ) * 16 + il    ] += acc[m][nn][0];
                tile[(j0    ) * 16 + il + 1] += acc[m][nn][1];
                tile[(j0 + 8) * 16 + il    ] += acc[m][nn][2];
                tile[(j0 + 8) * 16 + il + 1] += acc[m][nn][3];
            }
        }
    }
    __syncthreads();
    {   // contiguous 16 KB copy-out: g_part[h][ii][j][i16]
        float4*       dst4 = (float4*)(g_part + (h * 256 + ii) * 4096);
        const float4* src4 = (const float4*)tile;
#pragma unroll
        for (int k = 0; k < 4; k++) dst4[tid + 256 * k] = src4[tid + 256 * k];
    }
}

// ---------------------------------------------------------------------------
// Stage A: 131072 threads; sum 16 of 256 ii per (h, o). Coalesced. Determin.
// ---------------------------------------------------------------------------
__global__ void reduce_a_kernel() {
    const int gid = blockIdx.x * 256 + threadIdx.x;   // 0..131071
    const int o   = gid & 4095;
    const int seg = (gid >> 12) & 15;
    const int hh  = gid >> 16;
    const float* base = g_part + hh * (256 * 4096);
    float s0 = 0.f, s1 = 0.f, s2 = 0.f, s3 = 0.f;
#pragma unroll
    for (int cc = 0; cc < 16; cc += 4) {
        s0 += base[(seg * 16 + cc + 0) * 4096 + o];
        s1 += base[(seg * 16 + cc + 1) * 4096 + o];
        s2 += base[(seg * 16 + cc + 2) * 4096 + o];
        s3 += base[(seg * 16 + cc + 3) * 4096 + o];
    }
    g_red[(hh * 16 + seg) * 4096 + o] = (s0 + s1) + (s2 + s3);
}

// ---------------------------------------------------------------------------
// Stage B: fold 16 segments, write out[i][j] (transposed addressing, 32 KB).
// ---------------------------------------------------------------------------
__global__ void reduce_b_kernel(float* __restrict__ out) {
    const int gid = blockIdx.x * 256 + threadIdx.x;   // 0..8191
    const int o   = gid & 4095;
    const int hh  = gid >> 12;
    float s = 0.f;
#pragma unroll
    for (int g = 0; g < 16; g++) s += g_red[(hh * 16 + g) * 4096 + o];
    const int il = o & 15, j = o >> 4;
    out[(16 * hh + il) * OUT_W + j] = s;
}

// ---------------------------------------------------------------------------
extern "C" void kernel_launch(void* const* d_in, const int* in_sizes, int n_in,
                              void* d_out, int out_size) {
    const float* img = (const float*)d_in[0];   // [256, 512] f32
    const float* pos = (const float*)d_in[1];   // [2] f32
    float* out = (float*)d_out;                 // [32, 256] f32

    conv_mma_kernel<<<NBLK, 256, SMEM_BYTES>>>(img, pos);
    reduce_a_kernel<<<512, 256>>>();
    reduce_b_kernel<<<32, 256>>>(out);
}